// round 7
// baseline (speedup 1.0000x reference)
#include <cuda_runtime.h>
#include <cstdint>

// Problem constants
#define BB      8
#define NNODES  1024
#define HID     256
#define NHEADS  8
#define DH      32
#define EPER    16384
#define KPOOL   512

// Output layout (float32 concat, tuple order)
#define ENC_OFF   0          // 8*1024*256      = 2097152
#define SUBX_OFF  2097152    // 8*512*256       = 1048576
#define EDGE_OFF  3145728    // 8*2*16384       =  262144
#define PERM_OFF  3407872    // 8*512           =    4096
#define VAL_OFF   3411968    // 8*16384         =  131072

// Scratch (static device globals — no allocations, no symbol-address lookups)
__device__ float g_qkv[BB * NNODES * 768];   // Q|K|V fused, row stride 768
__device__ float g_ctx[BB * NNODES * HID];   // attention output pre-Wo
__device__ float g_wcat[HID * 768];          // [Wq|Wk|Wv] column-concat
__device__ float g_score[BB * NNODES];       // tanh pooling scores
__device__ int   g_perm[BB * KPOOL];
__device__ float g_vals[BB * KPOOL];
__device__ int   g_nodemap[BB * NNODES];
__device__ int   g_ekeys[BB * EPER];         // edge sort scratch
__device__ float g_wnorm;

// ---------------------------------------------------------------------------
// Accurate exp for x <= 0, ~1-2 ulp, immune to fast-math flag rewrites.
// ---------------------------------------------------------------------------
__device__ __forceinline__ float exp_acc(float x) {
    if (x < -80.0f) return 0.0f;
    float t = fmaf(x, 1.44269504088896340736f, 12582912.0f);
    float k = t - 12582912.0f;                 // rint(x * log2e)
    float r = fmaf(-k, 0.693359375f, x);       // x - k*ln2_hi
    r = fmaf(k, 2.12194440054690583e-4f, r);   // - k*ln2_lo (ln2 = hi - lo)
    float q = 1.0f / 5040.0f;
    q = fmaf(q, r, 1.0f / 720.0f);
    q = fmaf(q, r, 1.0f / 120.0f);
    q = fmaf(q, r, 1.0f / 24.0f);
    q = fmaf(q, r, 1.0f / 6.0f);
    q = fmaf(q, r, 0.5f);
    q = fmaf(q, r, 1.0f);
    q = fmaf(q, r, 1.0f);
    int ki = (int)k;
    float sc = __int_as_float((ki + 127) << 23);
    return q * sc;
}

// ---------------------------------------------------------------------------
// Wcat prep: g_wcat[k][j] = {Wq,Wk,Wv}[k][j%256]
// ---------------------------------------------------------------------------
__global__ void prep_wcat_kernel(const float* __restrict__ Wq,
                                 const float* __restrict__ Wk,
                                 const float* __restrict__ Wv) {
    int idx = blockIdx.x * 256 + threadIdx.x;   // 196608 total
    int k = idx / 768, j = idx % 768;
    int sel = j >> 8, col = j & 255;
    const float* W = (sel == 0) ? Wq : ((sel == 1) ? Wk : Wv);
    g_wcat[idx] = W[(k << 8) + col];
}

// ---------------------------------------------------------------------------
// fp32 tiled GEMM body: C[M,N] = A[M,K] * B[K,N], all row-major.
// BM=BN=64, BK=16, 256 threads, 4x4 microtile per thread.
// ---------------------------------------------------------------------------
__device__ __forceinline__
void gemm64_body(const float* __restrict__ A, const float* __restrict__ Bm,
                 float* __restrict__ C, int Nn, int Kd) {
    __shared__ float As[16][64];   // k-major (transposed in smem)
    __shared__ float Bs[16][64];
    int tid = threadIdx.x;
    int tx = tid & 15, ty = tid >> 4;
    int rowBase = blockIdx.y << 6, colBase = blockIdx.x << 6;

    float acc[4][4];
#pragma unroll
    for (int i = 0; i < 4; i++)
#pragma unroll
        for (int j = 0; j < 4; j++) acc[i][j] = 0.0f;

    int ar = tid >> 2, ak = (tid & 3) << 2;       // A loader: row, k-chunk
    int bk = tid >> 4, bc = (tid & 15) << 2;      // B loader: k-row, col-chunk
    const float* Aptr = A + (size_t)(rowBase + ar) * Kd + ak;
    const float* Bptr = Bm + (size_t)bk * Nn + colBase + bc;

    for (int k0 = 0; k0 < Kd; k0 += 16) {
        float4 fa = *(const float4*)(Aptr + k0);
        As[ak + 0][ar] = fa.x; As[ak + 1][ar] = fa.y;
        As[ak + 2][ar] = fa.z; As[ak + 3][ar] = fa.w;
        *(float4*)&Bs[bk][bc] = *(const float4*)(Bptr + (size_t)k0 * Nn);
        __syncthreads();
#pragma unroll
        for (int kk = 0; kk < 16; kk++) {
            float4 a = *(const float4*)&As[kk][ty << 2];
            float4 b = *(const float4*)&Bs[kk][tx << 2];
            acc[0][0] = fmaf(a.x, b.x, acc[0][0]); acc[0][1] = fmaf(a.x, b.y, acc[0][1]);
            acc[0][2] = fmaf(a.x, b.z, acc[0][2]); acc[0][3] = fmaf(a.x, b.w, acc[0][3]);
            acc[1][0] = fmaf(a.y, b.x, acc[1][0]); acc[1][1] = fmaf(a.y, b.y, acc[1][1]);
            acc[1][2] = fmaf(a.y, b.z, acc[1][2]); acc[1][3] = fmaf(a.y, b.w, acc[1][3]);
            acc[2][0] = fmaf(a.z, b.x, acc[2][0]); acc[2][1] = fmaf(a.z, b.y, acc[2][1]);
            acc[2][2] = fmaf(a.z, b.z, acc[2][2]); acc[2][3] = fmaf(a.z, b.w, acc[2][3]);
            acc[3][0] = fmaf(a.w, b.x, acc[3][0]); acc[3][1] = fmaf(a.w, b.y, acc[3][1]);
            acc[3][2] = fmaf(a.w, b.z, acc[3][2]); acc[3][3] = fmaf(a.w, b.w, acc[3][3]);
        }
        __syncthreads();
    }
#pragma unroll
    for (int i = 0; i < 4; i++) {
        float4 st = make_float4(acc[i][0], acc[i][1], acc[i][2], acc[i][3]);
        *(float4*)(C + (size_t)(rowBase + (ty << 2) + i) * Nn + colBase + (tx << 2)) = st;
    }
}

// QKV = emb @ g_wcat  (M=8192, N=768, K=256), scratch referenced directly
__global__ __launch_bounds__(256)
void gemm_qkv_kernel(const float* __restrict__ emb) {
    gemm64_body(emb, g_wcat, g_qkv, 768, 256);
}

// enc = g_ctx @ Wo  (M=8192, N=256, K=256), written straight into d_out
__global__ __launch_bounds__(256)
void gemm_wo_kernel(const float* __restrict__ Wo, float* __restrict__ enc) {
    gemm64_body(g_ctx, Wo, enc, 256, 256);
}

// ---------------------------------------------------------------------------
// Two-pass flash attention. Block = (b, 32-query tile), 256 threads.
// Thread t owns one (query, head) row: qi = t&31, h = t>>5.
// Dist bias tile shared across all 8 heads (read dist once, not 8x).
// ---------------------------------------------------------------------------
__global__ __launch_bounds__(256)
void flash_kernel(const float* __restrict__ dist) {
    __shared__ float Ks[16][256];
    __shared__ float Vs[16][256];
    __shared__ float Ds[32][17];

    int b = blockIdx.y, qt = blockIdx.x;
    int t = threadIdx.x;
    int qi = t & 31, h = t >> 5;
    int qrow = (b << 10) + (qt << 5) + qi;

    const float INVSQD = 0.17677669529663688110f;  // 1/sqrt(32)

    float qv[32];
    const float4* qp = (const float4*)(g_qkv + (size_t)qrow * 768 + (h << 5));
#pragma unroll
    for (int i = 0; i < 8; i++) {
        float4 f = qp[i];
        qv[4 * i] = f.x; qv[4 * i + 1] = f.y; qv[4 * i + 2] = f.z; qv[4 * i + 3] = f.w;
    }

    const float* kbase = g_qkv + ((size_t)(b << 10)) * 768 + 256;
    const float* vbase = g_qkv + ((size_t)(b << 10)) * 768 + 512;
    const float* dbase = dist + ((size_t)b << 20) + ((size_t)(qt << 5) << 10);

    // ---- pass 1: exact row max ----
    float m = -3.4e38f;
    for (int kt = 0; kt < 64; kt++) {
        const float* kb = kbase + (size_t)(kt << 4) * 768;
#pragma unroll
        for (int i = 0; i < 4; i++) {
            int s = t + (i << 8);
            int r = s >> 6, c = s & 63;
            *(float4*)&Ks[r][c << 2] = *(const float4*)(kb + (size_t)r * 768 + (c << 2));
        }
#pragma unroll
        for (int i = 0; i < 2; i++) {
            int s = t + (i << 8);
            int qr = s >> 4, kc = s & 15;
            Ds[qr][kc] = dbase[((size_t)qr << 10) + (kt << 4) + kc];
        }
        __syncthreads();
#pragma unroll
        for (int j = 0; j < 16; j++) {
            const float4* kp = (const float4*)&Ks[j][h << 5];
            float sc = 0.0f;
#pragma unroll
            for (int i = 0; i < 8; i++) {
                float4 f = kp[i];
                sc = fmaf(qv[4 * i], f.x, sc);
                sc = fmaf(qv[4 * i + 1], f.y, sc);
                sc = fmaf(qv[4 * i + 2], f.z, sc);
                sc = fmaf(qv[4 * i + 3], f.w, sc);
            }
            sc = fmaf(sc, INVSQD, Ds[qi][j]);
            m = fmaxf(m, sc);
        }
        __syncthreads();
    }

    // ---- pass 2: exp-sum and PV accumulate ----
    float l = 0.0f;
    float acc[32];
#pragma unroll
    for (int i = 0; i < 32; i++) acc[i] = 0.0f;

    for (int kt = 0; kt < 64; kt++) {
        const float* kb = kbase + (size_t)(kt << 4) * 768;
        const float* vb = vbase + (size_t)(kt << 4) * 768;
#pragma unroll
        for (int i = 0; i < 4; i++) {
            int s = t + (i << 8);
            int r = s >> 6, c = s & 63;
            *(float4*)&Ks[r][c << 2] = *(const float4*)(kb + (size_t)r * 768 + (c << 2));
            *(float4*)&Vs[r][c << 2] = *(const float4*)(vb + (size_t)r * 768 + (c << 2));
        }
#pragma unroll
        for (int i = 0; i < 2; i++) {
            int s = t + (i << 8);
            int qr = s >> 4, kc = s & 15;
            Ds[qr][kc] = dbase[((size_t)qr << 10) + (kt << 4) + kc];
        }
        __syncthreads();
#pragma unroll
        for (int j = 0; j < 16; j++) {
            const float4* kp = (const float4*)&Ks[j][h << 5];
            float sc = 0.0f;
#pragma unroll
            for (int i = 0; i < 8; i++) {
                float4 f = kp[i];
                sc = fmaf(qv[4 * i], f.x, sc);
                sc = fmaf(qv[4 * i + 1], f.y, sc);
                sc = fmaf(qv[4 * i + 2], f.z, sc);
                sc = fmaf(qv[4 * i + 3], f.w, sc);
            }
            sc = fmaf(sc, INVSQD, Ds[qi][j]);
            float p = exp_acc(sc - m);
            l += p;
            const float4* vp = (const float4*)&Vs[j][h << 5];
#pragma unroll
            for (int i = 0; i < 8; i++) {
                float4 f = vp[i];
                acc[4 * i]     = fmaf(p, f.x, acc[4 * i]);
                acc[4 * i + 1] = fmaf(p, f.y, acc[4 * i + 1]);
                acc[4 * i + 2] = fmaf(p, f.z, acc[4 * i + 2]);
                acc[4 * i + 3] = fmaf(p, f.w, acc[4 * i + 3]);
            }
        }
        __syncthreads();
    }

    float* op = g_ctx + (size_t)qrow * 256 + (h << 5);
#pragma unroll
    for (int i = 0; i < 32; i++) op[i] = acc[i] / l;
}

// ---------------------------------------------------------------------------
// ||w|| (single block)
// ---------------------------------------------------------------------------
__global__ void wnorm_kernel(const float* __restrict__ w) {
    __shared__ float sm[256];
    int t = threadIdx.x;
    float v = w[t];
    sm[t] = v * v;
    __syncthreads();
    for (int s = 128; s > 0; s >>= 1) {
        if (t < s) sm[t] += sm[t + s];
        __syncthreads();
    }
    if (t == 0) g_wnorm = sqrtf(sm[0]);
}

// ---------------------------------------------------------------------------
// Pooling scores: one warp per node, score = tanh(dot(x,w)/||w||)
// ---------------------------------------------------------------------------
__global__ __launch_bounds__(256)
void score_kernel(const float* __restrict__ enc, const float* __restrict__ w) {
    int node = (blockIdx.x << 3) + (threadIdx.x >> 5);
    int lane = threadIdx.x & 31;
    const float* xr = enc + (size_t)node * 256;
    float s = 0.0f;
#pragma unroll
    for (int i = 0; i < 8; i++) s = fmaf(xr[lane + (i << 5)], w[lane + (i << 5)], s);
#pragma unroll
    for (int o = 16; o > 0; o >>= 1) s += __shfl_down_sync(0xffffffffu, s, o);
    if (lane == 0) g_score[node] = tanhf(s / g_wnorm);
}

// ---------------------------------------------------------------------------
// Per-graph top-K via bitonic sort of 1024 (score desc, idx asc) keys.
// ---------------------------------------------------------------------------
__global__ __launch_bounds__(512)
void topk_kernel(float* __restrict__ out_perm) {
    __shared__ unsigned long long keys[1024];
    int b = blockIdx.x, t = threadIdx.x;
    for (int i = t; i < 1024; i += 512) {
        float s = g_score[(b << 10) + i];
        unsigned u = __float_as_uint(s);
        u = (u & 0x80000000u) ? ~u : (u | 0x80000000u);   // ascending map
        keys[i] = (((unsigned long long)(~u)) << 32) | (unsigned)i;  // desc score, asc idx
    }
    __syncthreads();
    for (int k = 2; k <= 1024; k <<= 1)
        for (int j = k >> 1; j > 0; j >>= 1) {
            for (int i = t; i < 1024; i += 512) {
                int ixj = i ^ j;
                if (ixj > i) {
                    unsigned long long a = keys[i], c = keys[ixj];
                    bool up = ((i & k) == 0);
                    if ((a > c) == up) { keys[i] = c; keys[ixj] = a; }
                }
            }
            __syncthreads();
        }
    for (int i = t; i < 1024; i += 512) {
        int n = (int)(keys[i] & 0xffffffffu);
        g_nodemap[(b << 10) + n] = (i < KPOOL) ? i : -1;
        if (i < KPOOL) {
            g_perm[(b << 9) + i] = n;
            g_vals[(b << 9) + i] = g_score[(b << 10) + n];
            out_perm[(b << 9) + i] = (float)n;
        }
    }
}

// ---------------------------------------------------------------------------
// sub_x gather: out[b,k,:] = enc[b,perm,:] * vals
// ---------------------------------------------------------------------------
__global__ void subx_kernel(const float* __restrict__ enc, float* __restrict__ out) {
    int blk = blockIdx.x;                 // 4096 rows
    int b = blk >> 9, kk = blk & 511;
    int n = g_perm[(b << 9) + kk] & 1023;          // defensive
    float val = g_vals[(b << 9) + kk];
    const float4* src = (const float4*)(enc + ((size_t)(b << 10) + n) * 256);
    float4* dst = (float4*)(out + (size_t)blk * 256);
    float4 f = src[threadIdx.x];
    dst[threadIdx.x] = make_float4(f.x * val, f.y * val, f.z * val, f.w * val);
}

// ---------------------------------------------------------------------------
// Edge remap + per-graph bitonic sort of 16384 int keys.
// edge_index is int32 per harness dtype rules (JAX x64 disabled downcasts
// jnp.int64 -> int32). A deterministic data probe handles the int64 case too:
// if the stream were little-endian int64 of values < 8192, every odd 32-bit
// word would be 0. Any out-of-range node id is treated as an invalid edge
// (SENT) instead of indexing scratch -> no wild accesses ever.
// Sort decomposed: per-half (8192 keys) bitonic in 32KB static smem, one
// cross-half global exchange, final within-half ascending merge + output.
// Tied keys produce identical output values, so any order within ties is OK.
// ---------------------------------------------------------------------------
__global__ __launch_bounds__(1024)
void edge_kernel(const int* __restrict__ ei,
                 float* __restrict__ out_e, float* __restrict__ out_v) {
    __shared__ int sk[8192];   // 32KB static
    __shared__ int s_mode;     // 0 = int32 stream, 1 = int64 stream
    int b = blockIdx.x, t = threadIdx.x;
    const int SENT = 0x7fffffff;
    int* gk = g_ekeys + b * EPER;

    if (t == 0) {
        int orv = 0;
#pragma unroll
        for (int i = 0; i < 64; i++) orv |= ei[2 * i + 1];
        s_mode = (orv == 0) ? 1 : 0;
    }
    __syncthreads();
    int mode = s_mode;

    for (int e = t; e < EPER; e += 1024) {
        int eg = b * EPER + e;
        int s, d;
        if (mode) {                       // int64 stream: take low words
            s = ei[2 * (size_t)eg];
            d = ei[2 * ((size_t)BB * EPER + eg)];
        } else {                          // int32 stream
            s = ei[eg];
            d = ei[(size_t)BB * EPER + eg];
        }
        int u = s - (b << 10);
        int v = d - (b << 10);
        int key = SENT;
        if ((unsigned)u < 1024u && (unsigned)v < 1024u) {
            int nu = g_nodemap[(b << 10) + u];
            int nv = g_nodemap[(b << 10) + v];
            if (nu >= 0 && nv >= 0) key = (nu << 9) | nv;
        }
        gk[e] = key;
    }
    __syncthreads();

    // Per-half: stages k=2..8192 in smem (k=8192 direction = half index)
    for (int h = 0; h < 2; h++) {
        for (int i = t; i < 8192; i += 1024) sk[i] = gk[(h << 13) + i];
        __syncthreads();
        for (int k = 2; k <= 8192; k <<= 1) {
            for (int j = k >> 1; j > 0; j >>= 1) {
                for (int i = t; i < 8192; i += 1024) {
                    int ixj = i ^ j;
                    if (ixj > i) {
                        bool up = (k == 8192) ? (h == 0) : ((i & k) == 0);
                        int a = sk[i], c = sk[ixj];
                        if ((a > c) == up) { sk[i] = c; sk[ixj] = a; }
                    }
                }
                __syncthreads();
            }
        }
        for (int i = t; i < 8192; i += 1024) gk[(h << 13) + i] = sk[i];
        __syncthreads();
    }

    // Cross-half exchange: k=16384, j=8192, ascending
    for (int i = t; i < 8192; i += 1024) {
        int a = gk[i], c = gk[i + 8192];
        if (a > c) { gk[i] = c; gk[i + 8192] = a; }
    }
    __syncthreads();

    // Final merge per half (j=4096..1, ascending) + output
    for (int h = 0; h < 2; h++) {
        for (int i = t; i < 8192; i += 1024) sk[i] = gk[(h << 13) + i];
        __syncthreads();
        for (int j = 4096; j > 0; j >>= 1) {
            for (int i = t; i < 8192; i += 1024) {
                int ixj = i ^ j;
                if (ixj > i) {
                    int a = sk[i], c = sk[ixj];
                    if (a > c) { sk[i] = c; sk[ixj] = a; }
                }
            }
            __syncthreads();
        }
        for (int i = t; i < 8192; i += 1024) {
            int kv = sk[i];
            int gi = (h << 13) + i;
            bool valid = (kv != SENT);
            out_e[(size_t)(b * 2) * EPER + gi]     = valid ? (float)(kv >> 9)  : -1.0f;
            out_e[(size_t)(b * 2 + 1) * EPER + gi] = valid ? (float)(kv & 511) : -1.0f;
            out_v[(size_t)b * EPER + gi] = valid ? 1.0f : 0.0f;
        }
        __syncthreads();
    }
}

// ---------------------------------------------------------------------------
// kernel_launch: ONLY kernel launches.
// ---------------------------------------------------------------------------
extern "C" void kernel_launch(void* const* d_in, const int* in_sizes, int n_in,
                              void* d_out, int out_size) {
    (void)in_sizes; (void)n_in; (void)out_size;
    const float* emb  = (const float*)d_in[0];
    const int*   eidx = (const int*)d_in[1];
    // d_in[2] = mask (all True, unused), d_in[4] = batch (unused)
    const float* dist = (const float*)d_in[3];
    const float* Wq   = (const float*)d_in[5];
    const float* Wk   = (const float*)d_in[6];
    const float* Wv   = (const float*)d_in[7];
    const float* Wo   = (const float*)d_in[8];
    const float* tw   = (const float*)d_in[9];

    float* out    = (float*)d_out;
    float* enc    = out + ENC_OFF;
    float* subx   = out + SUBX_OFF;
    float* oedge  = out + EDGE_OFF;
    float* operm  = out + PERM_OFF;
    float* ovalid = out + VAL_OFF;

    // 1. fuse projection weights, QKV = X @ [Wq|Wk|Wv]
    prep_wcat_kernel<<<768, 256>>>(Wq, Wk, Wv);
    gemm_qkv_kernel<<<dim3(768 / 64, 8192 / 64), 256>>>(emb);

    // 2. attention (two-pass flash, exact softmax max)
    flash_kernel<<<dim3(32, 8), 256>>>(dist);

    // 3. encoder_result = ctx @ Wo  (written straight into d_out)
    gemm_wo_kernel<<<dim3(256 / 64, 8192 / 64), 256>>>(Wo, enc);

    // 4. pooling scores + per-graph top-K
    wnorm_kernel<<<1, 256>>>(tw);
    score_kernel<<<1024, 256>>>(enc, tw);
    topk_kernel<<<BB, 512>>>(operm);

    // 5. gated gather of kept rows
    subx_kernel<<<BB * KPOOL, 64>>>(enc, subx);

    // 6. edge remap + sort + validity
    edge_kernel<<<BB, 1024>>>(eidx, oedge, ovalid);
}

// round 9
// speedup vs baseline: 1.1842x; 1.1842x over previous
#include <cuda_runtime.h>
#include <cstdint>

// Problem constants
#define BB      8
#define NNODES  1024
#define HID     256
#define NHEADS  8
#define DH      32
#define EPER    16384
#define KPOOL   512

// Output layout (float32 concat, tuple order)
#define ENC_OFF   0          // 8*1024*256      = 2097152
#define SUBX_OFF  2097152    // 8*512*256       = 1048576
#define EDGE_OFF  3145728    // 8*2*16384       =  262144
#define PERM_OFF  3407872    // 8*512           =    4096
#define VAL_OFF   3411968    // 8*16384         =  131072

typedef unsigned long long u64;

// Scratch (static device globals — no allocations, no symbol-address lookups)
__device__ float g_qkv[BB * NNODES * 768];   // Q|K|V fused, row stride 768
__device__ float g_ctx[BB * NNODES * HID];   // attention output pre-Wo
__device__ float g_wcat[HID * 768];          // [Wq|Wk|Wv] column-concat
__device__ float g_score[BB * NNODES];       // tanh pooling scores
__device__ int   g_perm[BB * KPOOL];
__device__ float g_vals[BB * KPOOL];
__device__ int   g_nodemap[BB * NNODES];
__device__ int   g_ekeys[BB * EPER];         // edge sort scratch
__device__ float g_wnorm;

// ---------------------------------------------------------------------------
// Packed f32x2 helpers (FFMA2: 2 fp32 FMAs per issue slot, bitwise-exact fp32)
// ---------------------------------------------------------------------------
__device__ __forceinline__ void fma2(u64& d, u64 a, u64 b) {
    asm("fma.rn.f32x2 %0, %1, %2, %0;" : "+l"(d) : "l"(a), "l"(b));
}
__device__ __forceinline__ u64 splat2(float v) {
    u64 r; asm("mov.b64 %0, {%1, %1};" : "=l"(r) : "f"(v)); return r;
}
__device__ __forceinline__ float2 unpk2(u64 v) {
    float2 f; asm("mov.b64 {%0, %1}, %2;" : "=f"(f.x), "=f"(f.y) : "l"(v)); return f;
}

// ---------------------------------------------------------------------------
// Accurate exp for x <= 0, ~1-2 ulp, immune to fast-math flag rewrites.
// ---------------------------------------------------------------------------
__device__ __forceinline__ float exp_acc(float x) {
    if (x < -80.0f) return 0.0f;
    float t = fmaf(x, 1.44269504088896340736f, 12582912.0f);
    float k = t - 12582912.0f;                 // rint(x * log2e)
    float r = fmaf(-k, 0.693359375f, x);       // x - k*ln2_hi
    r = fmaf(k, 2.12194440054690583e-4f, r);   // - k*ln2_lo (ln2 = hi - lo)
    float q = 1.0f / 5040.0f;
    q = fmaf(q, r, 1.0f / 720.0f);
    q = fmaf(q, r, 1.0f / 120.0f);
    q = fmaf(q, r, 1.0f / 24.0f);
    q = fmaf(q, r, 1.0f / 6.0f);
    q = fmaf(q, r, 0.5f);
    q = fmaf(q, r, 1.0f);
    q = fmaf(q, r, 1.0f);
    int ki = (int)k;
    float sc = __int_as_float((ki + 127) << 23);
    return q * sc;
}

// ---------------------------------------------------------------------------
// Wcat prep: g_wcat[k][j] = {Wq,Wk,Wv}[k][j%256]
// ---------------------------------------------------------------------------
__global__ void prep_wcat_kernel(const float* __restrict__ Wq,
                                 const float* __restrict__ Wk,
                                 const float* __restrict__ Wv) {
    int idx = blockIdx.x * 256 + threadIdx.x;   // 196608 total
    int k = idx / 768, j = idx % 768;
    int sel = j >> 8, col = j & 255;
    const float* W = (sel == 0) ? Wq : ((sel == 1) ? Wk : Wv);
    g_wcat[idx] = W[(k << 8) + col];
}

// ---------------------------------------------------------------------------
// fp32 tiled GEMM body with FFMA2: C[M,N] = A[M,K] * B[K,N], row-major.
// BM=BN=64, BK=16, 256 threads, 4x4 microtile per thread.
// A stored splat-duplicated in smem so both MMA operands load as packed pairs.
// Per-element accumulation order identical to scalar version (k-sequential).
// ---------------------------------------------------------------------------
__device__ __forceinline__
void gemm64_body(const float* __restrict__ A, const float* __restrict__ Bm,
                 float* __restrict__ C, int Nn, int Kd) {
    __shared__ float As2[16][128];  // k-major, each A value duplicated {v,v}
    __shared__ float Bs[16][64];
    int tid = threadIdx.x;
    int tx = tid & 15, ty = tid >> 4;
    int rowBase = blockIdx.y << 6, colBase = blockIdx.x << 6;

    u64 acc2[4][2];
#pragma unroll
    for (int i = 0; i < 4; i++) { acc2[i][0] = 0ull; acc2[i][1] = 0ull; }

    int ar = tid >> 2, ak = (tid & 3) << 2;       // A loader: row, k-chunk
    int bk = tid >> 4, bc = (tid & 15) << 2;      // B loader: k-row, col-chunk
    const float* Aptr = A + (size_t)(rowBase + ar) * Kd + ak;
    const float* Bptr = Bm + (size_t)bk * Nn + colBase + bc;

    for (int k0 = 0; k0 < Kd; k0 += 16) {
        float4 fa = *(const float4*)(Aptr + k0);
        *(float2*)&As2[ak + 0][ar << 1] = make_float2(fa.x, fa.x);
        *(float2*)&As2[ak + 1][ar << 1] = make_float2(fa.y, fa.y);
        *(float2*)&As2[ak + 2][ar << 1] = make_float2(fa.z, fa.z);
        *(float2*)&As2[ak + 3][ar << 1] = make_float2(fa.w, fa.w);
        *(float4*)&Bs[bk][bc] = *(const float4*)(Bptr + (size_t)k0 * Nn);
        __syncthreads();
#pragma unroll
        for (int kk = 0; kk < 16; kk++) {
            ulonglong2 a01 = *(const ulonglong2*)&As2[kk][ty << 3];
            ulonglong2 a23 = *(const ulonglong2*)&As2[kk][(ty << 3) + 4];
            ulonglong2 bb  = *(const ulonglong2*)&Bs[kk][tx << 2];
            fma2(acc2[0][0], a01.x, bb.x); fma2(acc2[0][1], a01.x, bb.y);
            fma2(acc2[1][0], a01.y, bb.x); fma2(acc2[1][1], a01.y, bb.y);
            fma2(acc2[2][0], a23.x, bb.x); fma2(acc2[2][1], a23.x, bb.y);
            fma2(acc2[3][0], a23.y, bb.x); fma2(acc2[3][1], a23.y, bb.y);
        }
        __syncthreads();
    }
#pragma unroll
    for (int i = 0; i < 4; i++) {
        float2 lo = unpk2(acc2[i][0]);
        float2 hi = unpk2(acc2[i][1]);
        *(float4*)(C + (size_t)(rowBase + (ty << 2) + i) * Nn + colBase + (tx << 2)) =
            make_float4(lo.x, lo.y, hi.x, hi.y);
    }
}

// QKV = emb @ g_wcat  (M=8192, N=768, K=256)
__global__ __launch_bounds__(256)
void gemm_qkv_kernel(const float* __restrict__ emb) {
    gemm64_body(emb, g_wcat, g_qkv, 768, 256);
}

// enc = g_ctx @ Wo  (M=8192, N=256, K=256), written straight into d_out
__global__ __launch_bounds__(256)
void gemm_wo_kernel(const float* __restrict__ Wo, float* __restrict__ enc) {
    gemm64_body(g_ctx, Wo, enc, 256, 256);
}

// ---------------------------------------------------------------------------
// Two-pass flash attention, FFMA2 math. Block = (b, 64-query tile), 512 thr.
// Thread t owns one (query, head) row: qi = t&63, h = t>>6.
// 128 blocks -> exactly one wave on 148 SMs. 36.4KB static smem.
// ---------------------------------------------------------------------------
__global__ __launch_bounds__(512)
void flash_kernel(const float* __restrict__ dist) {
    __shared__ float Ks[16][256];
    __shared__ float Vs[16][256];
    __shared__ float Ds[64][17];

    int b = blockIdx.y, qt = blockIdx.x;     // qt in 0..15
    int t = threadIdx.x;
    int qi = t & 63, h = t >> 6;
    int qrow = (b << 10) + (qt << 6) + qi;

    const float INVSQD = 0.17677669529663688110f;  // 1/sqrt(32)

    // Q row: 32 floats = 16 packed pairs
    u64 q2[16];
    const ulonglong2* qp = (const ulonglong2*)(g_qkv + (size_t)qrow * 768 + (h << 5));
#pragma unroll
    for (int i = 0; i < 8; i++) {
        ulonglong2 f = qp[i];
        q2[2 * i] = f.x; q2[2 * i + 1] = f.y;
    }

    const float* kbase = g_qkv + ((size_t)(b << 10)) * 768 + 256;
    const float* vbase = g_qkv + ((size_t)(b << 10)) * 768 + 512;
    const float* dbase = dist + ((size_t)b << 20) + ((size_t)(qt << 6) << 10);

    // ---- pass 1: exact row max ----
    float m = -3.4e38f;
    for (int kt = 0; kt < 64; kt++) {
        const float* kb = kbase + (size_t)(kt << 4) * 768;
#pragma unroll
        for (int i = 0; i < 2; i++) {
            int s = t + (i << 9);
            int r = s >> 6, c = s & 63;
            *(float4*)&Ks[r][c << 2] = *(const float4*)(kb + (size_t)r * 768 + (c << 2));
        }
#pragma unroll
        for (int i = 0; i < 2; i++) {
            int s = t + (i << 9);
            int qr = s >> 4, kc = s & 15;
            Ds[qr][kc] = dbase[((size_t)qr << 10) + (kt << 4) + kc];
        }
        __syncthreads();
#pragma unroll
        for (int j = 0; j < 16; j++) {
            const ulonglong2* kp = (const ulonglong2*)&Ks[j][h << 5];
            u64 sa = 0ull, sb = 0ull;           // two chains for ILP
#pragma unroll
            for (int i = 0; i < 8; i++) {
                ulonglong2 kx = kp[i];
                fma2(sa, q2[2 * i], kx.x);
                fma2(sb, q2[2 * i + 1], kx.y);
            }
            float2 fa = unpk2(sa), fb = unpk2(sb);
            float sc = (fa.x + fa.y) + (fb.x + fb.y);
            sc = fmaf(sc, INVSQD, Ds[qi][j]);
            m = fmaxf(m, sc);
        }
        __syncthreads();
    }

    // ---- pass 2: exp-sum and PV accumulate ----
    float l = 0.0f;
    u64 acc2[16];
#pragma unroll
    for (int i = 0; i < 16; i++) acc2[i] = 0ull;

    for (int kt = 0; kt < 64; kt++) {
        const float* kb = kbase + (size_t)(kt << 4) * 768;
        const float* vb = vbase + (size_t)(kt << 4) * 768;
#pragma unroll
        for (int i = 0; i < 2; i++) {
            int s = t + (i << 9);
            int r = s >> 6, c = s & 63;
            *(float4*)&Ks[r][c << 2] = *(const float4*)(kb + (size_t)r * 768 + (c << 2));
            *(float4*)&Vs[r][c << 2] = *(const float4*)(vb + (size_t)r * 768 + (c << 2));
        }
#pragma unroll
        for (int i = 0; i < 2; i++) {
            int s = t + (i << 9);
            int qr = s >> 4, kc = s & 15;
            Ds[qr][kc] = dbase[((size_t)qr << 10) + (kt << 4) + kc];
        }
        __syncthreads();
#pragma unroll
        for (int j = 0; j < 16; j++) {
            const ulonglong2* kp = (const ulonglong2*)&Ks[j][h << 5];
            u64 sa = 0ull, sb = 0ull;
#pragma unroll
            for (int i = 0; i < 8; i++) {
                ulonglong2 kx = kp[i];
                fma2(sa, q2[2 * i], kx.x);
                fma2(sb, q2[2 * i + 1], kx.y);
            }
            float2 fa = unpk2(sa), fb = unpk2(sb);
            float sc = (fa.x + fa.y) + (fb.x + fb.y);
            sc = fmaf(sc, INVSQD, Ds[qi][j]);
            float p = exp_acc(sc - m);
            l += p;
            u64 p2 = splat2(p);
            const ulonglong2* vp = (const ulonglong2*)&Vs[j][h << 5];
#pragma unroll
            for (int i = 0; i < 8; i++) {
                ulonglong2 vx = vp[i];
                fma2(acc2[2 * i], p2, vx.x);
                fma2(acc2[2 * i + 1], p2, vx.y);
            }
        }
        __syncthreads();
    }

    float invl = 1.0f;  // divide exactly as before: acc / l (no reciprocal)
    (void)invl;
    float* op = g_ctx + (size_t)qrow * 256 + (h << 5);
#pragma unroll
    for (int i = 0; i < 8; i++) {
        float2 f0 = unpk2(acc2[2 * i]);
        float2 f1 = unpk2(acc2[2 * i + 1]);
        *(float4*)(op + (i << 2)) =
            make_float4(f0.x / l, f0.y / l, f1.x / l, f1.y / l);
    }
}

// ---------------------------------------------------------------------------
// ||w|| (single block)
// ---------------------------------------------------------------------------
__global__ void wnorm_kernel(const float* __restrict__ w) {
    __shared__ float sm[256];
    int t = threadIdx.x;
    float v = w[t];
    sm[t] = v * v;
    __syncthreads();
    for (int s = 128; s > 0; s >>= 1) {
        if (t < s) sm[t] += sm[t + s];
        __syncthreads();
    }
    if (t == 0) g_wnorm = sqrtf(sm[0]);
}

// ---------------------------------------------------------------------------
// Pooling scores: one warp per node, score = tanh(dot(x,w)/||w||)
// ---------------------------------------------------------------------------
__global__ __launch_bounds__(256)
void score_kernel(const float* __restrict__ enc, const float* __restrict__ w) {
    int node = (blockIdx.x << 3) + (threadIdx.x >> 5);
    int lane = threadIdx.x & 31;
    const float* xr = enc + (size_t)node * 256;
    float s = 0.0f;
#pragma unroll
    for (int i = 0; i < 8; i++) s = fmaf(xr[lane + (i << 5)], w[lane + (i << 5)], s);
#pragma unroll
    for (int o = 16; o > 0; o >>= 1) s += __shfl_down_sync(0xffffffffu, s, o);
    if (lane == 0) g_score[node] = tanhf(s / g_wnorm);
}

// ---------------------------------------------------------------------------
// Per-graph top-K via bitonic sort of 1024 (score desc, idx asc) keys.
// ---------------------------------------------------------------------------
__global__ __launch_bounds__(512)
void topk_kernel(float* __restrict__ out_perm) {
    __shared__ unsigned long long keys[1024];
    int b = blockIdx.x, t = threadIdx.x;
    for (int i = t; i < 1024; i += 512) {
        float s = g_score[(b << 10) + i];
        unsigned u = __float_as_uint(s);
        u = (u & 0x80000000u) ? ~u : (u | 0x80000000u);   // ascending map
        keys[i] = (((unsigned long long)(~u)) << 32) | (unsigned)i;  // desc score, asc idx
    }
    __syncthreads();
    for (int k = 2; k <= 1024; k <<= 1)
        for (int j = k >> 1; j > 0; j >>= 1) {
            for (int i = t; i < 1024; i += 512) {
                int ixj = i ^ j;
                if (ixj > i) {
                    unsigned long long a = keys[i], c = keys[ixj];
                    bool up = ((i & k) == 0);
                    if ((a > c) == up) { keys[i] = c; keys[ixj] = a; }
                }
            }
            __syncthreads();
        }
    for (int i = t; i < 1024; i += 512) {
        int n = (int)(keys[i] & 0xffffffffu);
        g_nodemap[(b << 10) + n] = (i < KPOOL) ? i : -1;
        if (i < KPOOL) {
            g_perm[(b << 9) + i] = n;
            g_vals[(b << 9) + i] = g_score[(b << 10) + n];
            out_perm[(b << 9) + i] = (float)n;
        }
    }
}

// ---------------------------------------------------------------------------
// sub_x gather: out[b,k,:] = enc[b,perm,:] * vals
// ---------------------------------------------------------------------------
__global__ void subx_kernel(const float* __restrict__ enc, float* __restrict__ out) {
    int blk = blockIdx.x;                 // 4096 rows
    int b = blk >> 9, kk = blk & 511;
    int n = g_perm[(b << 9) + kk] & 1023;          // defensive
    float val = g_vals[(b << 9) + kk];
    const float4* src = (const float4*)(enc + ((size_t)(b << 10) + n) * 256);
    float4* dst = (float4*)(out + (size_t)blk * 256);
    float4 f = src[threadIdx.x];
    dst[threadIdx.x] = make_float4(f.x * val, f.y * val, f.z * val, f.w * val);
}

// ---------------------------------------------------------------------------
// Edge pipeline, 2 kernels x 16 blocks (one block per (graph, half)).
// Kernel 1: remap + per-half bitonic sort of 8192 keys in 32KB static smem.
//           Half 0 ends ascending, half 1 descending -> global bitonic seq.
// Kernel 2: cross-half exchange (min/max vs partner, read-only of other half)
//           + final ascending merge j=4096..1 + output writes.
// edge_index dtype probed at runtime (int32 per harness rules; int64 stream
// would have all-zero odd words). Out-of-range ids -> invalid (no wild loads).
// ---------------------------------------------------------------------------
__global__ __launch_bounds__(1024)
void edge_sort_kernel(const int* __restrict__ ei) {
    __shared__ int sk[8192];   // 32KB
    __shared__ int s_mode;
    int blk = blockIdx.x;
    int b = blk >> 1, h = blk & 1;
    int t = threadIdx.x;
    const int SENT = 0x7fffffff;

    if (t == 0) {
        int orv = 0;
#pragma unroll
        for (int i = 0; i < 64; i++) orv |= ei[2 * i + 1];
        s_mode = (orv == 0) ? 1 : 0;
    }
    __syncthreads();
    int mode = s_mode;

    for (int l = t; l < 8192; l += 1024) {
        int eg = b * EPER + (h << 13) + l;
        int s, d;
        if (mode) {                       // int64 stream: low words
            s = ei[2 * (size_t)eg];
            d = ei[2 * ((size_t)BB * EPER + eg)];
        } else {                          // int32 stream
            s = ei[eg];
            d = ei[(size_t)BB * EPER + eg];
        }
        int u = s - (b << 10);
        int v = d - (b << 10);
        int key = SENT;
        if ((unsigned)u < 1024u && (unsigned)v < 1024u) {
            int nu = g_nodemap[(b << 10) + u];
            int nv = g_nodemap[(b << 10) + v];
            if (nu >= 0 && nv >= 0) key = (nu << 9) | nv;
        }
        sk[l] = key;
    }
    __syncthreads();

    for (int k = 2; k <= 8192; k <<= 1) {
        for (int j = k >> 1; j > 0; j >>= 1) {
            for (int l = t; l < 8192; l += 1024) {
                int ixj = l ^ j;
                if (ixj > l) {
                    bool up = (k == 8192) ? (h == 0) : ((l & k) == 0);
                    int a = sk[l], c = sk[ixj];
                    if ((a > c) == up) { sk[l] = c; sk[ixj] = a; }
                }
            }
            __syncthreads();
        }
    }
    for (int l = t; l < 8192; l += 1024) g_ekeys[b * EPER + (h << 13) + l] = sk[l];
}

__global__ __launch_bounds__(1024)
void edge_merge_kernel(float* __restrict__ out_e, float* __restrict__ out_v) {
    __shared__ int sk[8192];
    int blk = blockIdx.x;
    int b = blk >> 1, h = blk & 1;
    int t = threadIdx.x;
    const int SENT = 0x7fffffff;
    const int* gk = g_ekeys + b * EPER;

    // cross-half exchange (k=16384, j=8192, ascending): low half keeps min
    for (int l = t; l < 8192; l += 1024) {
        int a = gk[(h << 13) + l];
        int p = gk[((1 - h) << 13) + l];
        sk[l] = h ? ((a > p) ? a : p) : ((a < p) ? a : p);
    }
    __syncthreads();

    for (int j = 4096; j > 0; j >>= 1) {
        for (int l = t; l < 8192; l += 1024) {
            int ixj = l ^ j;
            if (ixj > l) {
                int a = sk[l], c = sk[ixj];
                if (a > c) { sk[l] = c; sk[ixj] = a; }
            }
        }
        __syncthreads();
    }

    for (int l = t; l < 8192; l += 1024) {
        int kv = sk[l];
        int gi = (h << 13) + l;
        bool valid = (kv != SENT);
        out_e[(size_t)(b * 2) * EPER + gi]     = valid ? (float)(kv >> 9)  : -1.0f;
        out_e[(size_t)(b * 2 + 1) * EPER + gi] = valid ? (float)(kv & 511) : -1.0f;
        out_v[(size_t)b * EPER + gi] = valid ? 1.0f : 0.0f;
    }
}

// ---------------------------------------------------------------------------
// kernel_launch: ONLY kernel launches.
// ---------------------------------------------------------------------------
extern "C" void kernel_launch(void* const* d_in, const int* in_sizes, int n_in,
                              void* d_out, int out_size) {
    (void)in_sizes; (void)n_in; (void)out_size;
    const float* emb  = (const float*)d_in[0];
    const int*   eidx = (const int*)d_in[1];
    // d_in[2] = mask (all True, unused), d_in[4] = batch (unused)
    const float* dist = (const float*)d_in[3];
    const float* Wq   = (const float*)d_in[5];
    const float* Wk   = (const float*)d_in[6];
    const float* Wv   = (const float*)d_in[7];
    const float* Wo   = (const float*)d_in[8];
    const float* tw   = (const float*)d_in[9];

    float* out    = (float*)d_out;
    float* enc    = out + ENC_OFF;
    float* subx   = out + SUBX_OFF;
    float* oedge  = out + EDGE_OFF;
    float* operm  = out + PERM_OFF;
    float* ovalid = out + VAL_OFF;

    // 1. fuse projection weights, QKV = X @ [Wq|Wk|Wv]
    prep_wcat_kernel<<<768, 256>>>(Wq, Wk, Wv);
    gemm_qkv_kernel<<<dim3(768 / 64, 8192 / 64), 256>>>(emb);

    // 2. attention (two-pass flash, exact softmax max, FFMA2 math)
    flash_kernel<<<dim3(16, 8), 512>>>(dist);

    // 3. encoder_result = ctx @ Wo  (written straight into d_out)
    gemm_wo_kernel<<<dim3(256 / 64, 8192 / 64), 256>>>(Wo, enc);

    // 4. pooling scores + per-graph top-K
    wnorm_kernel<<<1, 256>>>(tw);
    score_kernel<<<1024, 256>>>(enc, tw);
    topk_kernel<<<BB, 512>>>(operm);

    // 5. gated gather of kept rows
    subx_kernel<<<BB * KPOOL, 64>>>(enc, subx);

    // 6. edge remap + sort + validity (2-phase, 16 blocks each)
    edge_sort_kernel<<<2 * BB, 1024>>>(eidx);
    edge_merge_kernel<<<2 * BB, 1024>>>(oedge, ovalid);
}

// round 11
// speedup vs baseline: 1.6340x; 1.3798x over previous
#include <cuda_runtime.h>
#include <cstdint>

// Problem constants
#define BB      8
#define NNODES  1024
#define HID     256
#define NHEADS  8
#define DH      32
#define EPER    16384
#define KPOOL   512

// Output layout (float32 concat, tuple order)
#define ENC_OFF   0          // 8*1024*256      = 2097152
#define SUBX_OFF  2097152    // 8*512*256       = 1048576
#define EDGE_OFF  3145728    // 8*2*16384       =  262144
#define PERM_OFF  3407872    // 8*512           =    4096
#define VAL_OFF   3411968    // 8*16384         =  131072

typedef unsigned long long u64;

// Scratch (static device globals — no allocations, no symbol-address lookups)
__device__ float g_qkv[BB * NNODES * 768];   // Q|K|V fused, row stride 768
__device__ float g_ctx[BB * NNODES * HID];   // attention output pre-Wo
__device__ float g_wcat[HID * 768];          // [Wq|Wk|Wv] column-concat
__device__ float g_score[BB * NNODES];       // tanh pooling scores
__device__ float g_dmax[BB * NNODES];        // per-(b,q) row max of dist
__device__ float g_kmax[BB * NHEADS];        // per-(b,h) max ||k||
__device__ int   g_perm[BB * KPOOL];
__device__ float g_vals[BB * KPOOL];
__device__ int   g_nodemap[BB * NNODES];
__device__ int   g_ekeys[BB * EPER];         // edge sort scratch
__device__ float g_wnorm;

// ---------------------------------------------------------------------------
// Packed f32x2 helpers (FFMA2: 2 fp32 FMAs per issue slot, bitwise-exact fp32)
// ---------------------------------------------------------------------------
__device__ __forceinline__ void fma2(u64& d, u64 a, u64 b) {
    asm("fma.rn.f32x2 %0, %1, %2, %0;" : "+l"(d) : "l"(a), "l"(b));
}
__device__ __forceinline__ u64 splat2(float v) {
    u64 r; asm("mov.b64 %0, {%1, %1};" : "=l"(r) : "f"(v)); return r;
}
__device__ __forceinline__ float2 unpk2(u64 v) {
    float2 f; asm("mov.b64 {%0, %1}, %2;" : "=f"(f.x), "=f"(f.y) : "l"(v)); return f;
}

// ---------------------------------------------------------------------------
// Accurate exp for x <= 0 (plus tiny positive slack), ~1-2 ulp.
// ---------------------------------------------------------------------------
__device__ __forceinline__ float exp_acc(float x) {
    if (x < -80.0f) return 0.0f;
    float t = fmaf(x, 1.44269504088896340736f, 12582912.0f);
    float k = t - 12582912.0f;                 // rint(x * log2e)
    float r = fmaf(-k, 0.693359375f, x);       // x - k*ln2_hi
    r = fmaf(k, 2.12194440054690583e-4f, r);   // - k*ln2_lo (ln2 = hi - lo)
    float q = 1.0f / 5040.0f;
    q = fmaf(q, r, 1.0f / 720.0f);
    q = fmaf(q, r, 1.0f / 120.0f);
    q = fmaf(q, r, 1.0f / 24.0f);
    q = fmaf(q, r, 1.0f / 6.0f);
    q = fmaf(q, r, 0.5f);
    q = fmaf(q, r, 1.0f);
    q = fmaf(q, r, 1.0f);
    int ki = (int)k;
    float sc = __int_as_float((ki + 127) << 23);
    return q * sc;
}

// ---------------------------------------------------------------------------
// Wcat prep: g_wcat[k][j] = {Wq,Wk,Wv}[k][j%256]
// ---------------------------------------------------------------------------
__global__ void prep_wcat_kernel(const float* __restrict__ Wq,
                                 const float* __restrict__ Wk,
                                 const float* __restrict__ Wv) {
    int idx = blockIdx.x * 256 + threadIdx.x;   // 196608 total
    int k = idx / 768, j = idx % 768;
    int sel = j >> 8, col = j & 255;
    const float* W = (sel == 0) ? Wq : ((sel == 1) ? Wk : Wv);
    g_wcat[idx] = W[(k << 8) + col];
}

// ---------------------------------------------------------------------------
// fp32 GEMM, FFMA2: C[M,N] = A[M,K] * B[K,N], row-major.
// BM=BN=128, BK=16, 256 threads, 8x8 microtile per thread.
// Smem is scalar (no duplication); A splat into u64 pairs via register MOV.
// acc pairs packed along N; per-element accumulation is k-sequential ->
// numerics identical to a scalar FFMA loop.
// ---------------------------------------------------------------------------
__device__ __forceinline__
void gemm128_body(const float* __restrict__ A, const float* __restrict__ Bm,
                  float* __restrict__ C, int Nn, int Kd) {
    __shared__ float As[16][132];   // k-major (A transposed), pad 4
    __shared__ float Bs[16][128];
    int tid = threadIdx.x;
    int tx = tid & 15, ty = tid >> 4;   // tx: n-tile, ty: m-tile
    int rowBase = blockIdx.y << 7, colBase = blockIdx.x << 7;

    u64 acc2[8][4];
#pragma unroll
    for (int i = 0; i < 8; i++)
#pragma unroll
        for (int j = 0; j < 4; j++) acc2[i][j] = 0ull;

    int ar = tid >> 2, ak = (tid & 3) << 2;       // A loader: row(0..63), k-chunk
    int bk = tid >> 4, bc = (tid & 15) << 3;      // B loader: k-row, col-chunk
    const float* Aptr = A + (size_t)(rowBase + ar) * Kd + ak;
    const float* Bptr = Bm + (size_t)bk * Nn + colBase + bc;

    for (int k0 = 0; k0 < Kd; k0 += 16) {
#pragma unroll
        for (int p = 0; p < 2; p++) {
            float4 fa = *(const float4*)(Aptr + (size_t)(p << 6) * Kd + k0);
            int row = ar + (p << 6);
            As[ak + 0][row] = fa.x; As[ak + 1][row] = fa.y;
            As[ak + 2][row] = fa.z; As[ak + 3][row] = fa.w;
        }
        {
            const float* bsrc = Bptr + (size_t)k0 * Nn;
            *(float4*)&Bs[bk][bc]     = *(const float4*)(bsrc);
            *(float4*)&Bs[bk][bc + 4] = *(const float4*)(bsrc + 4);
        }
        __syncthreads();
#pragma unroll
        for (int kk = 0; kk < 16; kk++) {
            float4 a0 = *(const float4*)&As[kk][ty << 3];
            float4 a1 = *(const float4*)&As[kk][(ty << 3) + 4];
            ulonglong2 b0 = *(const ulonglong2*)&Bs[kk][tx << 3];
            ulonglong2 b1 = *(const ulonglong2*)&Bs[kk][(tx << 3) + 4];
            u64 s0 = splat2(a0.x), s1 = splat2(a0.y);
            u64 s2 = splat2(a0.z), s3 = splat2(a0.w);
            u64 s4 = splat2(a1.x), s5 = splat2(a1.y);
            u64 s6 = splat2(a1.z), s7 = splat2(a1.w);
            fma2(acc2[0][0], s0, b0.x); fma2(acc2[0][1], s0, b0.y);
            fma2(acc2[0][2], s0, b1.x); fma2(acc2[0][3], s0, b1.y);
            fma2(acc2[1][0], s1, b0.x); fma2(acc2[1][1], s1, b0.y);
            fma2(acc2[1][2], s1, b1.x); fma2(acc2[1][3], s1, b1.y);
            fma2(acc2[2][0], s2, b0.x); fma2(acc2[2][1], s2, b0.y);
            fma2(acc2[2][2], s2, b1.x); fma2(acc2[2][3], s2, b1.y);
            fma2(acc2[3][0], s3, b0.x); fma2(acc2[3][1], s3, b0.y);
            fma2(acc2[3][2], s3, b1.x); fma2(acc2[3][3], s3, b1.y);
            fma2(acc2[4][0], s4, b0.x); fma2(acc2[4][1], s4, b0.y);
            fma2(acc2[4][2], s4, b1.x); fma2(acc2[4][3], s4, b1.y);
            fma2(acc2[5][0], s5, b0.x); fma2(acc2[5][1], s5, b0.y);
            fma2(acc2[5][2], s5, b1.x); fma2(acc2[5][3], s5, b1.y);
            fma2(acc2[6][0], s6, b0.x); fma2(acc2[6][1], s6, b0.y);
            fma2(acc2[6][2], s6, b1.x); fma2(acc2[6][3], s6, b1.y);
            fma2(acc2[7][0], s7, b0.x); fma2(acc2[7][1], s7, b0.y);
            fma2(acc2[7][2], s7, b1.x); fma2(acc2[7][3], s7, b1.y);
        }
        __syncthreads();
    }
#pragma unroll
    for (int i = 0; i < 8; i++) {
        float* crow = C + (size_t)(rowBase + (ty << 3) + i) * Nn + colBase + (tx << 3);
        float2 p0 = unpk2(acc2[i][0]);
        float2 p1 = unpk2(acc2[i][1]);
        float2 p2 = unpk2(acc2[i][2]);
        float2 p3 = unpk2(acc2[i][3]);
        *(float4*)(crow)     = make_float4(p0.x, p0.y, p1.x, p1.y);
        *(float4*)(crow + 4) = make_float4(p2.x, p2.y, p3.x, p3.y);
    }
}

// QKV = emb @ g_wcat  (M=8192, N=768, K=256)
__global__ __launch_bounds__(256)
void gemm_qkv_kernel(const float* __restrict__ emb) {
    gemm128_body(emb, g_wcat, g_qkv, 768, 256);
}

// enc = g_ctx @ Wo  (M=8192, N=256, K=256), written straight into d_out
__global__ __launch_bounds__(256)
void gemm_wo_kernel(const float* __restrict__ Wo, float* __restrict__ enc) {
    gemm128_body(g_ctx, Wo, enc, 256, 256);
}

// ---------------------------------------------------------------------------
// dist row max: one warp per (b,q) row
// ---------------------------------------------------------------------------
__global__ __launch_bounds__(256)
void dmax_kernel(const float* __restrict__ dist) {
    int r = (blockIdx.x << 3) + (threadIdx.x >> 5);   // 8192 rows
    int lane = threadIdx.x & 31;
    const float* row = dist + (size_t)r * 1024;
    float m = -3.4e38f;
#pragma unroll
    for (int i = 0; i < 32; i++) m = fmaxf(m, row[(i << 5) + lane]);
#pragma unroll
    for (int o = 16; o > 0; o >>= 1)
        m = fmaxf(m, __shfl_xor_sync(0xffffffffu, m, o));
    if (lane == 0) g_dmax[r] = m;
}

// ---------------------------------------------------------------------------
// per-(b,h) max ||k||: 64 blocks, 256 threads scan 1024 K rows
// ---------------------------------------------------------------------------
__global__ __launch_bounds__(256)
void kmax_kernel() {
    __shared__ float sm[256];
    int blk = blockIdx.x;                // b*8 + h
    int b = blk >> 3, h = blk & 7;
    int t = threadIdx.x;
    float best = 0.0f;
    for (int n = t; n < 1024; n += 256) {
        const float4* kp = (const float4*)(g_qkv + ((size_t)(b << 10) + n) * 768
                                           + 256 + (h << 5));
        float s = 0.0f;
#pragma unroll
        for (int i = 0; i < 8; i++) {
            float4 f = kp[i];
            s = fmaf(f.x, f.x, s); s = fmaf(f.y, f.y, s);
            s = fmaf(f.z, f.z, s); s = fmaf(f.w, f.w, s);
        }
        best = fmaxf(best, s);
    }
    sm[t] = best;
    __syncthreads();
    for (int s = 128; s > 0; s >>= 1) {
        if (t < s) sm[t] = fmaxf(sm[t], sm[t + s]);
        __syncthreads();
    }
    if (t == 0) g_kmax[blk] = sqrtf(sm[0]);
}

// ---------------------------------------------------------------------------
// Single-pass flash attention with Cauchy-Schwarz max bound.
// m' = dmax[b,q] + ||q||*kmax[b,h]/sqrt(d) >= true row max; softmax output is
// invariant to the shift, exp args stay in (-40, ~0] -> full fp32 precision.
// Block = (b, 64-query tile), 512 threads; qi = t&63, h = t>>6.
// ---------------------------------------------------------------------------
__global__ __launch_bounds__(512)
void flash_kernel(const float* __restrict__ dist) {
    __shared__ float Ks[16][256];
    __shared__ float Vs[16][256];
    __shared__ float Ds[64][17];

    int b = blockIdx.y, qt = blockIdx.x;     // qt in 0..15
    int t = threadIdx.x;
    int qi = t & 63, h = t >> 6;
    int qrow = (b << 10) + (qt << 6) + qi;

    const float INVSQD = 0.17677669529663688110f;  // 1/sqrt(32)

    // Q row: 32 floats = 16 packed pairs
    u64 q2[16];
    const ulonglong2* qp = (const ulonglong2*)(g_qkv + (size_t)qrow * 768 + (h << 5));
#pragma unroll
    for (int i = 0; i < 8; i++) {
        ulonglong2 f = qp[i];
        q2[2 * i] = f.x; q2[2 * i + 1] = f.y;
    }

    // upper bound on row max
    u64 nn = 0ull;
#pragma unroll
    for (int i = 0; i < 16; i++) fma2(nn, q2[i], q2[i]);
    float2 nf = unpk2(nn);
    float qn = sqrtf(nf.x + nf.y);
    float m = fmaf(qn * g_kmax[(b << 3) + h], INVSQD, g_dmax[qrow]);

    const float* kbase = g_qkv + ((size_t)(b << 10)) * 768 + 256;
    const float* vbase = g_qkv + ((size_t)(b << 10)) * 768 + 512;
    const float* dbase = dist + ((size_t)b << 20) + ((size_t)(qt << 6) << 10);

    float l = 0.0f;
    u64 acc2[16];
#pragma unroll
    for (int i = 0; i < 16; i++) acc2[i] = 0ull;

    for (int kt = 0; kt < 64; kt++) {
        const float* kb = kbase + (size_t)(kt << 4) * 768;
        const float* vb = vbase + (size_t)(kt << 4) * 768;
#pragma unroll
        for (int i = 0; i < 2; i++) {
            int s = t + (i << 9);
            int r = s >> 6, c = s & 63;
            *(float4*)&Ks[r][c << 2] = *(const float4*)(kb + (size_t)r * 768 + (c << 2));
            *(float4*)&Vs[r][c << 2] = *(const float4*)(vb + (size_t)r * 768 + (c << 2));
        }
#pragma unroll
        for (int i = 0; i < 2; i++) {
            int s = t + (i << 9);
            int qr = s >> 4, kc = s & 15;
            Ds[qr][kc] = dbase[((size_t)qr << 10) + (kt << 4) + kc];
        }
        __syncthreads();
#pragma unroll
        for (int j = 0; j < 16; j++) {
            const ulonglong2* kp = (const ulonglong2*)&Ks[j][h << 5];
            u64 sa = 0ull, sb = 0ull;           // two chains for ILP
#pragma unroll
            for (int i = 0; i < 8; i++) {
                ulonglong2 kx = kp[i];
                fma2(sa, q2[2 * i], kx.x);
                fma2(sb, q2[2 * i + 1], kx.y);
            }
            float2 fa = unpk2(sa), fb = unpk2(sb);
            float sc = (fa.x + fa.y) + (fb.x + fb.y);
            sc = fmaf(sc, INVSQD, Ds[qi][j]);
            float p = exp_acc(sc - m);
            l += p;
            u64 p2 = splat2(p);
            const ulonglong2* vp = (const ulonglong2*)&Vs[j][h << 5];
#pragma unroll
            for (int i = 0; i < 8; i++) {
                ulonglong2 vx = vp[i];
                fma2(acc2[2 * i], p2, vx.x);
                fma2(acc2[2 * i + 1], p2, vx.y);
            }
        }
        __syncthreads();
    }

    float* op = g_ctx + (size_t)qrow * 256 + (h << 5);
#pragma unroll
    for (int i = 0; i < 8; i++) {
        float2 f0 = unpk2(acc2[2 * i]);
        float2 f1 = unpk2(acc2[2 * i + 1]);
        *(float4*)(op + (i << 2)) =
            make_float4(f0.x / l, f0.y / l, f1.x / l, f1.y / l);
    }
}

// ---------------------------------------------------------------------------
// ||w|| (single block)
// ---------------------------------------------------------------------------
__global__ void wnorm_kernel(const float* __restrict__ w) {
    __shared__ float sm[256];
    int t = threadIdx.x;
    float v = w[t];
    sm[t] = v * v;
    __syncthreads();
    for (int s = 128; s > 0; s >>= 1) {
        if (t < s) sm[t] += sm[t + s];
        __syncthreads();
    }
    if (t == 0) g_wnorm = sqrtf(sm[0]);
}

// ---------------------------------------------------------------------------
// Pooling scores: one warp per node, score = tanh(dot(x,w)/||w||)
// ---------------------------------------------------------------------------
__global__ __launch_bounds__(256)
void score_kernel(const float* __restrict__ enc, const float* __restrict__ w) {
    int node = (blockIdx.x << 3) + (threadIdx.x >> 5);
    int lane = threadIdx.x & 31;
    const float* xr = enc + (size_t)node * 256;
    float s = 0.0f;
#pragma unroll
    for (int i = 0; i < 8; i++) s = fmaf(xr[lane + (i << 5)], w[lane + (i << 5)], s);
#pragma unroll
    for (int o = 16; o > 0; o >>= 1) s += __shfl_down_sync(0xffffffffu, s, o);
    if (lane == 0) g_score[node] = tanhf(s / g_wnorm);
}

// ---------------------------------------------------------------------------
// Per-graph top-K via bitonic sort of 1024 (score desc, idx asc) keys.
// ---------------------------------------------------------------------------
__global__ __launch_bounds__(512)
void topk_kernel(float* __restrict__ out_perm) {
    __shared__ unsigned long long keys[1024];
    int b = blockIdx.x, t = threadIdx.x;
    for (int i = t; i < 1024; i += 512) {
        float s = g_score[(b << 10) + i];
        unsigned u = __float_as_uint(s);
        u = (u & 0x80000000u) ? ~u : (u | 0x80000000u);   // ascending map
        keys[i] = (((unsigned long long)(~u)) << 32) | (unsigned)i;  // desc score, asc idx
    }
    __syncthreads();
    for (int k = 2; k <= 1024; k <<= 1)
        for (int j = k >> 1; j > 0; j >>= 1) {
            for (int i = t; i < 1024; i += 512) {
                int ixj = i ^ j;
                if (ixj > i) {
                    unsigned long long a = keys[i], c = keys[ixj];
                    bool up = ((i & k) == 0);
                    if ((a > c) == up) { keys[i] = c; keys[ixj] = a; }
                }
            }
            __syncthreads();
        }
    for (int i = t; i < 1024; i += 512) {
        int n = (int)(keys[i] & 0xffffffffu);
        g_nodemap[(b << 10) + n] = (i < KPOOL) ? i : -1;
        if (i < KPOOL) {
            g_perm[(b << 9) + i] = n;
            g_vals[(b << 9) + i] = g_score[(b << 10) + n];
            out_perm[(b << 9) + i] = (float)n;
        }
    }
}

// ---------------------------------------------------------------------------
// sub_x gather: out[b,k,:] = enc[b,perm,:] * vals
// ---------------------------------------------------------------------------
__global__ void subx_kernel(const float* __restrict__ enc, float* __restrict__ out) {
    int blk = blockIdx.x;                 // 4096 rows
    int b = blk >> 9, kk = blk & 511;
    int n = g_perm[(b << 9) + kk] & 1023;          // defensive
    float val = g_vals[(b << 9) + kk];
    const float4* src = (const float4*)(enc + ((size_t)(b << 10) + n) * 256);
    float4* dst = (float4*)(out + (size_t)blk * 256);
    float4 f = src[threadIdx.x];
    dst[threadIdx.x] = make_float4(f.x * val, f.y * val, f.z * val, f.w * val);
}

// ---------------------------------------------------------------------------
// Edge pipeline, 2 kernels x 16 blocks (one block per (graph, half)).
// Kernel 1: remap + per-half bitonic sort of 8192 keys in 32KB static smem.
// Kernel 2: cross-half exchange + final ascending merge + output writes.
// edge_index dtype probed at runtime (int32 per harness rules; int64 stream
// would have all-zero odd words). Out-of-range ids -> invalid (no wild loads).
// ---------------------------------------------------------------------------
__global__ __launch_bounds__(1024)
void edge_sort_kernel(const int* __restrict__ ei) {
    __shared__ int sk[8192];   // 32KB
    __shared__ int s_mode;
    int blk = blockIdx.x;
    int b = blk >> 1, h = blk & 1;
    int t = threadIdx.x;
    const int SENT = 0x7fffffff;

    if (t == 0) {
        int orv = 0;
#pragma unroll
        for (int i = 0; i < 64; i++) orv |= ei[2 * i + 1];
        s_mode = (orv == 0) ? 1 : 0;
    }
    __syncthreads();
    int mode = s_mode;

    for (int l = t; l < 8192; l += 1024) {
        int eg = b * EPER + (h << 13) + l;
        int s, d;
        if (mode) {                       // int64 stream: low words
            s = ei[2 * (size_t)eg];
            d = ei[2 * ((size_t)BB * EPER + eg)];
        } else {                          // int32 stream
            s = ei[eg];
            d = ei[(size_t)BB * EPER + eg];
        }
        int u = s - (b << 10);
        int v = d - (b << 10);
        int key = SENT;
        if ((unsigned)u < 1024u && (unsigned)v < 1024u) {
            int nu = g_nodemap[(b << 10) + u];
            int nv = g_nodemap[(b << 10) + v];
            if (nu >= 0 && nv >= 0) key = (nu << 9) | nv;
        }
        sk[l] = key;
    }
    __syncthreads();

    for (int k = 2; k <= 8192; k <<= 1) {
        for (int j = k >> 1; j > 0; j >>= 1) {
            for (int l = t; l < 8192; l += 1024) {
                int ixj = l ^ j;
                if (ixj > l) {
                    bool up = (k == 8192) ? (h == 0) : ((l & k) == 0);
                    int a = sk[l], c = sk[ixj];
                    if ((a > c) == up) { sk[l] = c; sk[ixj] = a; }
                }
            }
            __syncthreads();
        }
    }
    for (int l = t; l < 8192; l += 1024) g_ekeys[b * EPER + (h << 13) + l] = sk[l];
}

__global__ __launch_bounds__(1024)
void edge_merge_kernel(float* __restrict__ out_e, float* __restrict__ out_v) {
    __shared__ int sk[8192];
    int blk = blockIdx.x;
    int b = blk >> 1, h = blk & 1;
    int t = threadIdx.x;
    const int SENT = 0x7fffffff;
    const int* gk = g_ekeys + b * EPER;

    // cross-half exchange (k=16384, j=8192, ascending): low half keeps min
    for (int l = t; l < 8192; l += 1024) {
        int a = gk[(h << 13) + l];
        int p = gk[((1 - h) << 13) + l];
        sk[l] = h ? ((a > p) ? a : p) : ((a < p) ? a : p);
    }
    __syncthreads();

    for (int j = 4096; j > 0; j >>= 1) {
        for (int l = t; l < 8192; l += 1024) {
            int ixj = l ^ j;
            if (ixj > l) {
                int a = sk[l], c = sk[ixj];
                if (a > c) { sk[l] = c; sk[ixj] = a; }
            }
        }
        __syncthreads();
    }

    for (int l = t; l < 8192; l += 1024) {
        int kv = sk[l];
        int gi = (h << 13) + l;
        bool valid = (kv != SENT);
        out_e[(size_t)(b * 2) * EPER + gi]     = valid ? (float)(kv >> 9)  : -1.0f;
        out_e[(size_t)(b * 2 + 1) * EPER + gi] = valid ? (float)(kv & 511) : -1.0f;
        out_v[(size_t)b * EPER + gi] = valid ? 1.0f : 0.0f;
    }
}

// ---------------------------------------------------------------------------
// kernel_launch: ONLY kernel launches.
// ---------------------------------------------------------------------------
extern "C" void kernel_launch(void* const* d_in, const int* in_sizes, int n_in,
                              void* d_out, int out_size) {
    (void)in_sizes; (void)n_in; (void)out_size;
    const float* emb  = (const float*)d_in[0];
    const int*   eidx = (const int*)d_in[1];
    // d_in[2] = mask (all True, unused), d_in[4] = batch (unused)
    const float* dist = (const float*)d_in[3];
    const float* Wq   = (const float*)d_in[5];
    const float* Wk   = (const float*)d_in[6];
    const float* Wv   = (const float*)d_in[7];
    const float* Wo   = (const float*)d_in[8];
    const float* tw   = (const float*)d_in[9];

    float* out    = (float*)d_out;
    float* enc    = out + ENC_OFF;
    float* subx   = out + SUBX_OFF;
    float* oedge  = out + EDGE_OFF;
    float* operm  = out + PERM_OFF;
    float* ovalid = out + VAL_OFF;

    // 1. fuse projection weights, QKV = X @ [Wq|Wk|Wv]
    prep_wcat_kernel<<<768, 256>>>(Wq, Wk, Wv);
    gemm_qkv_kernel<<<dim3(768 / 128, 8192 / 128), 256>>>(emb);

    // 2. softmax max-bound inputs, then single-pass flash attention
    dmax_kernel<<<1024, 256>>>(dist);
    kmax_kernel<<<BB * NHEADS, 256>>>();
    flash_kernel<<<dim3(16, 8), 512>>>(dist);

    // 3. encoder_result = ctx @ Wo  (written straight into d_out)
    gemm_wo_kernel<<<dim3(256 / 128, 8192 / 128), 256>>>(Wo, enc);

    // 4. pooling scores + per-graph top-K
    wnorm_kernel<<<1, 256>>>(tw);
    score_kernel<<<1024, 256>>>(enc, tw);
    topk_kernel<<<BB, 512>>>(operm);

    // 5. gated gather of kept rows
    subx_kernel<<<BB * KPOOL, 64>>>(enc, subx);

    // 6. edge remap + sort + validity (2-phase, 16 blocks each)
    edge_sort_kernel<<<2 * BB, 1024>>>(eidx);
    edge_merge_kernel<<<2 * BB, 1024>>>(oedge, ovalid);
}